// round 1
// baseline (speedup 1.0000x reference)
#include <cuda_runtime.h>
#include <math.h>

#define Bv   64
#define Tv   500
#define Hh   128
#define Kk   32
#define NSK  101    /* N_SK+1 */
#define BT   (Bv*Tv)

/* ---------------- scratch (device globals; no allocation) ---------------- */
__device__ float d_sedata [BT*Hh];
__device__ float d_selearn[BT*Hh];
__device__ float d_gx     [BT*3*Hh];
__device__ float d_preg   [BT*Hh];
__device__ float d_pregg  [BT*Hh];
__device__ float d_wall   [BT*Kk];
__device__ float d_gruout [BT*Hh];
__device__ float d_out1   [Bv*(Tv-1)*Hh];

__device__ float d_W1T [256*128];
__device__ float d_W2T [384*128];
__device__ float d_W3T [256*128];
__device__ float d_WihT[128*384];
__device__ float d_keyT[128*32];
__device__ float d_WGgT[128*256];   /* [j][o]: o<128 -> Wg[o][j], else Wgg[o-128][j]  (ht half) */
__device__ float d_WgTl [128*128];  /* learning half of Wg  */
__device__ float d_WggTl[128*128];  /* learning half of Wgg */
__device__ float d_WfTa [128*128];  /* Wf[:, :128]  transposed */
__device__ float d_WfTb [128*128];  /* Wf[:, 128:]  transposed */
__device__ float d_whhT [128*384];

__device__ __forceinline__ float sigm(float x){ return 1.f/(1.f+expf(-x)); }

/* ---------------- weight pre-transpose ---------------- */
__global__ void prep_kernel(const float* W1, const float* W2, const float* W3,
                            const float* key, const float* wih, const float* whh,
                            const float* Wg, const float* Wgg, const float* Wf)
{
    int stride = gridDim.x*blockDim.x;
    int t0 = blockIdx.x*blockDim.x + threadIdx.x;
    for (int i=t0;i<256*128;i+=stride){ int j=i>>7,h=i&127; d_W1T[i]=W1[h*256+j]; d_W3T[i]=W3[h*256+j]; }
    for (int i=t0;i<384*128;i+=stride){ int j=i>>7,h=i&127; d_W2T[i]=W2[h*384+j]; }
    for (int i=t0;i<128*384;i+=stride){ int h=i/384,g=i%384; d_WihT[i]=wih[g*128+h]; d_whhT[i]=whh[g*128+h]; }
    for (int i=t0;i<128*32;i+=stride){ int h=i>>5,k=i&31; d_keyT[i]=key[k*128+h]; }
    for (int i=t0;i<128*256;i+=stride){ int j=i>>8,o=i&255;
        d_WGgT[i] = (o<128)? Wg[o*256+j] : Wgg[(o-128)*256+j]; }
    for (int i=t0;i<128*128;i+=stride){ int j=i>>7,h=i&127;
        d_WgTl[i]=Wg[h*256+128+j]; d_WggTl[i]=Wgg[h*256+128+j];
        d_WfTa[i]=Wf[h*256+j];     d_WfTb[i]=Wf[h*256+128+j]; }
}

/* ---------------- fused parallel phase: embeddings + all per-(b,t) linears ----------------
   16 rows per block, 256 threads: thread = (h in [0,128), rh in {0,1} -> 8 rows each). */
__global__ void __launch_bounds__(256) fused_kernel(
    const int* e_data, const int* a_data, const float* qm, const float* semb_w,
    const float* aemb_w, const float* eemb_w,
    const float* b1, const float* b2, const float* b3,
    const float* bih, const float* bg, const float* bgg)
{
    __shared__ float X [16*384];   /* [s_emb | e_emb | a_emb] ; later reused for e_learning [16*128] */
    __shared__ float sd[16*128];   /* se_data  */
    __shared__ float sl[16*128];   /* se_learning */
    int tid = threadIdx.x;
    int h = tid & 127, rh = tid >> 7;
    int base = blockIdx.x*16;
    int rbase = rh*8;

    /* phase 0: embeddings (s_emb computed from q_matrix row of e) */
    for (int r8=0;r8<8;r8++){
        int rr = rbase + r8; int row = base + rr;
        int e = e_data[row], a = a_data[row];
        const float* qrow = qm + (size_t)e*NSK;
        float acc=0.f, cnt=0.f;
        #pragma unroll 4
        for (int s=0;s<NSK;s++){ float q = qrow[s]; acc += q*semb_w[s*128+h]; cnt += q; }
        if (cnt==0.f) cnt=1.f;
        X[rr*384+h]       = acc/cnt;
        X[rr*384+128+h]   = eemb_w[e*128+h];
        X[rr*384+256+h]   = aemb_w[a*128+h];
    }
    __syncthreads();

    /* se_data = relu([s,e] @ W1^T + b1) */
    {
        float acc[8];
        #pragma unroll
        for(int r=0;r<8;r++)acc[r]=b1[h];
        #pragma unroll 4
        for (int j=0;j<256;j++){ float w = d_W1T[j*128+h];
            #pragma unroll
            for (int r=0;r<8;r++) acc[r] += X[(rbase+r)*384 + j]*w; }
        #pragma unroll
        for (int r=0;r<8;r++){ float v=fmaxf(acc[r],0.f);
            sd[(rbase+r)*128+h]=v; d_sedata[(base+rbase+r)*128+h]=v; }
    }
    /* se_learning = relu([s,e,a] @ W2^T + b2) */
    {
        float acc[8];
        #pragma unroll
        for(int r=0;r<8;r++)acc[r]=b2[h];
        #pragma unroll 4
        for (int j=0;j<384;j++){ float w = d_W2T[j*128+h];
            #pragma unroll
            for (int r=0;r<8;r++) acc[r] += X[(rbase+r)*384 + j]*w; }
        #pragma unroll
        for (int r=0;r<8;r++){ float v=fmaxf(acc[r],0.f);
            sl[(rbase+r)*128+h]=v; d_selearn[(base+rbase+r)*128+h]=v; }
    }
    /* e_learning = relu([e,a] @ W3^T + b3)  (kept in regs, then parked in X) */
    float el[8];
    {
        float acc[8];
        #pragma unroll
        for(int r=0;r<8;r++)acc[r]=b3[h];
        #pragma unroll 4
        for (int j=0;j<256;j++){ float w = d_W3T[j*128+h];
            #pragma unroll
            for (int r=0;r<8;r++) acc[r] += X[(rbase+r)*384 + 128 + j]*w; }
        #pragma unroll
        for (int r=0;r<8;r++) el[r] = fmaxf(acc[r],0.f);
    }
    __syncthreads();
    #pragma unroll
    for (int r=0;r<8;r++) X[(rbase+r)*128 + h] = el[r];
    __syncthreads();

    /* gx = e_learning @ w_ih^T + b_ih  (3H outputs) */
    for (int p=0;p<3;p++){
        int g = p*128+h;
        float acc[8];
        #pragma unroll
        for(int r=0;r<8;r++)acc[r]=bih[g];
        #pragma unroll 4
        for (int j=0;j<128;j++){ float w = d_WihT[j*384+g];
            #pragma unroll
            for (int r=0;r<8;r++) acc[r] += X[(rbase+r)*128+j]*w; }
        #pragma unroll
        for (int r=0;r<8;r++) d_gx[(base+rbase+r)*384 + g] = acc[r];
    }
    /* pre_g / pre_gg: learning-half of Wg/Wgg + biases */
    {
        float a1[8],a2[8];
        #pragma unroll
        for(int r=0;r<8;r++){a1[r]=bg[h]; a2[r]=bgg[h];}
        #pragma unroll 4
        for (int j=0;j<128;j++){ float w1=d_WgTl[j*128+h], w2=d_WggTl[j*128+h];
            #pragma unroll
            for (int r=0;r<8;r++){ float x=sl[(rbase+r)*128+j]; a1[r]+=x*w1; a2[r]+=x*w2; } }
        #pragma unroll
        for (int r=0;r<8;r++){ d_preg[(base+rbase+r)*128+h]=a1[r]; d_pregg[(base+rbase+r)*128+h]=a2[r]; }
    }
    /* Wall = se_data @ key^T */
    if (tid < 64){
        int k = tid & 31; int rh2 = tid >> 5; int rb2 = rh2*8;
        float acc[8];
        #pragma unroll
        for(int r=0;r<8;r++)acc[r]=0.f;
        #pragma unroll 4
        for (int j=0;j<128;j++){ float w = d_keyT[j*32+k];
            #pragma unroll
            for (int r=0;r<8;r++) acc[r] += sd[(rb2+r)*128+j]*w; }
        #pragma unroll
        for (int r=0;r<8;r++) d_wall[(base+rb2+r)*32 + k] = acc[r];
    }
}

/* ---------------- sequential scans: blocks 0..63 memory scan, 64..127 GRU ---------------- */
#define SMEM_FLOATS 54912   /* 219648 bytes */

__global__ void __launch_bounds__(512) scan_kernel(
    const float* h0, const float* m0, const float* bf, const float* bhh)
{
    extern __shared__ float sm[];
    int tid = threadIdx.x;
    int b = blockIdx.x & 63;

    if (blockIdx.x < 64) {
        /* ------------- memory scan (one batch per CTA) ------------- */
        float* WGg = sm;             /* 32768 : [j][256] gates (ht half) */
        float* Wfa = sm + 32768;     /* 16384 : Wf_a^T [j][128] */
        float* hs  = sm + 49152;     /* 4096  : h state [k][h] */
        float* htv = sm + 53248;     /* 128 */
        float* gn  = sm + 53376;     /* 128 */
        float* gt  = sm + 53504;     /* 128 */
        float* LG  = sm + 53632;     /* 128 */
        float* cv  = sm + 53760;     /* 128 */
        float* scr = sm + 53888;     /* 1024 */

        for (int i=tid;i<32768;i+=512) WGg[i] = d_WGgT[i];
        for (int i=tid;i<16384;i+=512) Wfa[i] = d_WfTa[i];
        for (int i=tid;i<4096; i+=512) hs [i] = m0[i];
        __syncthreads();

        /* ht0 = Wall[b,0] . h_pre0 */
        if (tid < 128){
            float acc=0.f; const float* w0 = d_wall + b*Tv*Kk;
            #pragma unroll 8
            for (int k=0;k<32;k++) acc += w0[k]*hs[k*128+tid];
            htv[tid]=acc;
        }
        __syncthreads();

        int hq = tid & 31, kq = tid >> 5;
        int h0i = hq*4, k0 = kq*4;

        for (int t=0;t<Tv-1;t++){
            /* A) gate dots on ht (all 512 threads, split-2 over j) */
            { int o = tid & 255, half = tid >> 8; int j0 = half*64;
              float acc=0.f;
              #pragma unroll 8
              for (int j=0;j<64;j++) acc += WGg[(j0+j)*256+o]*htv[j0+j];
              scr[half*256+o]=acc; }
            __syncthreads();
            if (tid<256){ float s = scr[tid]+scr[256+tid];
                if (tid<128) gn[tid] = tanhf(s + d_preg [(b*Tv+t)*128+tid]);
                else         gt[tid-128] = sigm(s + d_pregg[(b*Tv+t)*128+tid-128]); }
            __syncthreads();
            if (tid<128) LG[tid] = gn[tid]*gt[tid];
            __syncthreads();
            /* B) c = Wf_b @ LG + bf  (weights from L2) */
            { int hh = tid & 127, q = tid >> 7; int j0 = q*32;
              float acc=0.f;
              #pragma unroll 8
              for (int j=0;j<32;j++) acc += d_WfTb[(j0+j)*128+hh]*LG[j0+j];
              scr[q*128+hh]=acc; }
            __syncthreads();
            if (tid<128) cv[tid] = scr[tid]+scr[128+tid]+scr[256+tid]+scr[384+tid] + bf[tid];
            __syncthreads();

            /* C) main GEMM: acc[k][h] = h_pre[k,:] . Wf_a[h,:]   (4k x 4h per thread) */
            float acc[4][4];
            if (tid<256){
                #pragma unroll
                for(int a=0;a<4;a++){
                    #pragma unroll
                    for(int c=0;c<4;c++)acc[a][c]=0.f;
                }
                #pragma unroll 4
                for (int j=0;j<128;j++){
                    float4 wv = *(const float4*)&Wfa[j*128 + h0i];
                    float hp0 = hs[(k0+0)*128+j];
                    float hp1 = hs[(k0+1)*128+j];
                    float hp2 = hs[(k0+2)*128+j];
                    float hp3 = hs[(k0+3)*128+j];
                    acc[0][0]+=hp0*wv.x; acc[0][1]+=hp0*wv.y; acc[0][2]+=hp0*wv.z; acc[0][3]+=hp0*wv.w;
                    acc[1][0]+=hp1*wv.x; acc[1][1]+=hp1*wv.y; acc[1][2]+=hp1*wv.z; acc[1][3]+=hp1*wv.w;
                    acc[2][0]+=hp2*wv.x; acc[2][1]+=hp2*wv.y; acc[2][2]+=hp2*wv.z; acc[2][3]+=hp2*wv.w;
                    acc[3][0]+=hp3*wv.x; acc[3][1]+=hp3*wv.y; acc[3][2]+=hp3*wv.z; acc[3][3]+=hp3*wv.w;
                }
            }
            __syncthreads();   /* all reads of old hs complete */
            if (tid<256){
                const float* wr = d_wall + (b*Tv+t)*Kk;
                const float* wn = wr + Kk;
                float pr[4]={0.f,0.f,0.f,0.f};
                #pragma unroll
                for (int kk=0;kk<4;kk++){
                    float wtk = wr[k0+kk], wnk = wn[k0+kk];
                    #pragma unroll
                    for (int a=0;a<4;a++){
                        int hc = h0i+a;
                        float g  = sigm(acc[kk][a] + cv[hc]);
                        float hn = g*hs[(k0+kk)*128+hc] + wtk*LG[hc];
                        hs[(k0+kk)*128+hc] = hn;
                        pr[a] += wnk*hn;
                    }
                }
                #pragma unroll
                for (int a=0;a<4;a++) scr[kq*128 + h0i + a] = pr[a];
            }
            __syncthreads();
            if (tid<128){
                float s=0.f;
                #pragma unroll
                for(int q=0;q<8;q++) s += scr[q*128+tid];
                htv[tid]=s;
                d_out1[(b*(Tv-1)+t)*128 + tid] = s;
            }
            __syncthreads();
        }
    } else {
        /* ------------- GRU scan (one batch per CTA) ------------- */
        float* whh = sm;            /* 49152 : w_hh^T [j][384] */
        float* hv  = sm + 49152;    /* 128 */
        float* gh  = sm + 49280;    /* 384 */
        for (int i=tid;i<49152;i+=512) whh[i]=d_whhT[i];
        if (tid<128) hv[tid]=h0[tid];
        __syncthreads();
        for (int t=0;t<Tv;t++){
            if (tid<384){
                float acc = bhh[tid];
                #pragma unroll 8
                for (int j=0;j<128;j++) acc += whh[j*384+tid]*hv[j];
                gh[tid]=acc;
            }
            __syncthreads();
            if (tid<128){
                const float* gx = d_gx + (b*Tv+t)*384;
                float r = sigm(gx[tid]     + gh[tid]);
                float z = sigm(gx[128+tid] + gh[128+tid]);
                float n = tanhf(gx[256+tid] + r*gh[256+tid]);
                float hn = (1.f-z)*n + z*hv[tid];
                hv[tid]=hn;
                d_gruout[(b*Tv+t)*128+tid]=hn;
            }
            __syncthreads();
        }
    }
}

/* ---------------- prediction head ---------------- */
__global__ void __launch_bounds__(256) final_kernel(
    const int* e_data, const float* eemb_w, const float* Wp, const float* bp,
    const float* Wp1, const float* bp1, float* out)
{
    int w = blockIdx.x*8 + (threadIdx.x>>5);
    int lane = threadIdx.x & 31;
    if (w >= Bv*(Tv-1)) return;
    int b = w/(Tv-1), tm = w%(Tv-1); int t1 = tm+1;
    int e = e_data[b*Tv + t1];
    float a0=0.f, a1=0.f;
    for (int d=lane; d<384; d+=32){
        float xo = 0.f;
        if (d<128)       xo = d_gruout[(b*Tv+tm)*128+d];
        else if (d<256)  xo = d_out1[(b*(Tv-1)+tm)*128 + d-128];
        float x  = (d<256)? xo : eemb_w[e*128 + d-256];
        float x1 = (d<256)? xo : d_sedata[(b*Tv+t1)*128 + d-256];
        a0 += Wp[d]*x; a1 += Wp1[d]*x1;
    }
    #pragma unroll
    for (int off=16;off;off>>=1){
        a0 += __shfl_down_sync(0xffffffffu,a0,off);
        a1 += __shfl_down_sync(0xffffffffu,a1,off);
    }
    if (lane==0){
        float r  = sigm(a0+bp[0]);
        float r1 = sigm(a1+bp1[0]);
        out[b*Tv + t1] = r*r1;
        if (tm==0) out[b*Tv] = 0.f;
    }
}

/* ---------------- launch ---------------- */
extern "C" void kernel_launch(void* const* d_in, const int* in_sizes, int n_in,
                              void* d_out, int out_size)
{
    const int*   a_data   = (const int*)  d_in[1];
    const int*   e_data   = (const int*)  d_in[2];
    const float* q_matrix = (const float*)d_in[4];
    const float* semb_w   = (const float*)d_in[5];
    const float* aemb_w   = (const float*)d_in[6];
    const float* eemb_w   = (const float*)d_in[7];
    const float* W1=(const float*)d_in[8];  const float* b1=(const float*)d_in[9];
    const float* W2=(const float*)d_in[10]; const float* b2=(const float*)d_in[11];
    const float* W3=(const float*)d_in[12]; const float* b3=(const float*)d_in[13];
    const float* key=(const float*)d_in[14];
    const float* wih=(const float*)d_in[15]; const float* whh=(const float*)d_in[16];
    const float* bih=(const float*)d_in[17]; const float* bhh=(const float*)d_in[18];
    const float* Wg=(const float*)d_in[19];  const float* bg=(const float*)d_in[20];
    const float* Wgg=(const float*)d_in[21]; const float* bgg=(const float*)d_in[22];
    const float* Wf=(const float*)d_in[23];  const float* bf=(const float*)d_in[24];
    const float* Wp=(const float*)d_in[25];  const float* bp=(const float*)d_in[26];
    const float* Wp1=(const float*)d_in[27]; const float* bp1=(const float*)d_in[28];
    const float* h0=(const float*)d_in[29];  const float* m0=(const float*)d_in[30];
    float* out = (float*)d_out;

    cudaFuncSetAttribute(scan_kernel, cudaFuncAttributeMaxDynamicSharedMemorySize,
                         SMEM_FLOATS*(int)sizeof(float));

    prep_kernel <<<64,  256>>>(W1,W2,W3,key,wih,whh,Wg,Wgg,Wf);
    fused_kernel<<<2000,256>>>(e_data,a_data,q_matrix,semb_w,aemb_w,eemb_w,
                               b1,b2,b3,bih,bg,bgg);
    scan_kernel <<<128, 512, SMEM_FLOATS*(int)sizeof(float)>>>(h0,m0,bf,bhh);
    final_kernel<<<3992,256>>>(e_data,eemb_w,Wp,bp,Wp1,bp1,out);
}